// round 5
// baseline (speedup 1.0000x reference)
#include <cuda_runtime.h>

#define NB   32
#define CIN  64
#define COUT 128
#define HW   4096               // 64*64 spatial per (n,ci)
#define INV_OHW (1.0f/4489.0f)  // 1/(67*67)
#define NXB  (NB * CIN)         // 2048 x-reduce blocks
#define GRID (NB + NXB)         // 32 finalize blocks FIRST, then x blocks

__device__ float g_Sx[NB * CIN];
__device__ unsigned g_count = 0;   // x-block arrivals
__device__ unsigned g_done  = 0;   // finalize-block completions

__device__ __forceinline__ void atom_inc_release(unsigned* p) {
    unsigned old;
    asm volatile("atom.add.release.gpu.u32 %0, [%1], 1;"
                 : "=r"(old) : "l"(p) : "memory");
}
__device__ __forceinline__ unsigned ld_acquire(const unsigned* p) {
    unsigned v;
    asm volatile("ld.acquire.gpu.u32 %0, [%1];" : "=r"(v) : "l"(p) : "memory");
    return v;
}

__device__ __forceinline__ float warp_sum(float v) {
    v += __shfl_xor_sync(0xffffffffu, v, 16);
    v += __shfl_xor_sync(0xffffffffu, v, 8);
    v += __shfl_xor_sync(0xffffffffu, v, 4);
    v += __shfl_xor_sync(0xffffffffu, v, 2);
    v += __shfl_xor_sync(0xffffffffu, v, 1);
    return v;
}
__device__ __forceinline__ float warp_max(float v) {
    v = fmaxf(v, __shfl_xor_sync(0xffffffffu, v, 16));
    v = fmaxf(v, __shfl_xor_sync(0xffffffffu, v, 8));
    v = fmaxf(v, __shfl_xor_sync(0xffffffffu, v, 4));
    v = fmaxf(v, __shfl_xor_sync(0xffffffffu, v, 2));
    v = fmaxf(v, __shfl_xor_sync(0xffffffffu, v, 1));
    return v;
}

__global__ void __launch_bounds__(256) fused_kernel(
    const float* __restrict__ x,
    const float* __restrict__ w,
    const float* __restrict__ cb,
    const float* __restrict__ eb,
    float* __restrict__ out)
{
    __shared__ float sh_sw[CIN * COUT];   // 32KB: finalize blocks' Sw
    __shared__ float sh_misc[CIN];        // x: cross-warp scratch / fin: sx row
    __shared__ float red[4], red2[4];

    const int bid  = blockIdx.x;
    const int t    = threadIdx.x;
    const int lane = t & 31;
    const int wid  = t >> 5;

    if (bid >= NB) {
        // ---------------- x-reduce block ----------------
        const int b = bid - NB;   // (n,ci) pair index
        const float4* p = reinterpret_cast<const float4*>(x) + (size_t)b * (HW / 4);
        float s = 0.0f;
        #pragma unroll
        for (int i = 0; i < 4; i++) {
            float4 v = p[t + i * 256];
            s += (v.x + v.y) + (v.z + v.w);
        }
        s = warp_sum(s);
        if (lane == 0) sh_misc[wid] = s;
        __syncthreads();
        if (t == 0) {
            float u = ((sh_misc[0] + sh_misc[1]) + (sh_misc[2] + sh_misc[3]))
                    + ((sh_misc[4] + sh_misc[5]) + (sh_misc[6] + sh_misc[7]));
            g_Sx[b] = u;                 // thread0's own store...
            atom_inc_release(&g_count);  // ...ordered by its release-atomic
        }
        return;
    }

    // ---------------- finalize block: n = bid ----------------
    const int n  = bid;
    const int co = t;   // t in [0,256); only t<128 active for channel work

    // Prefetch biases early (overlaps everything below).
    float bias = 0.0f;
    if (co < COUT) bias = cb[co] + eb[co];

    // Reduce the whole weight tensor into smem (L2-hot after first block).
    for (int idx = t; idx < CIN * COUT; idx += 256) {
        const float4* wp = reinterpret_cast<const float4*>(w) + (size_t)idx * 4;
        float4 a0 = wp[0], a1 = wp[1], a2 = wp[2], a3 = wp[3];
        sh_sw[idx] =
            ((a0.x + a0.y) + (a0.z + a0.w)) +
            ((a1.x + a1.y) + (a1.z + a1.w)) +
            ((a2.x + a2.y) + (a2.z + a2.w)) +
            ((a3.x + a3.y) + (a3.z + a3.w));
    }

    // Wait for all x-blocks (acquire pairs with their release-atomics).
    if (t == 0) {
        while (ld_acquire(&g_count) < NXB) __nanosleep(64);
    }
    __syncthreads();

    // Stage this batch row's Sx.
    if (t < CIN) sh_misc[t] = __ldcg(&g_Sx[n * CIN + t]);
    __syncthreads();

    if (co < COUT) {
        float a0 = 0.f, a1 = 0.f, a2 = 0.f, a3 = 0.f;
        #pragma unroll
        for (int ci = 0; ci < CIN; ci += 4) {
            a0 = fmaf(sh_misc[ci + 0], sh_sw[(ci + 0) * COUT + co], a0);
            a1 = fmaf(sh_misc[ci + 1], sh_sw[(ci + 1) * COUT + co], a1);
            a2 = fmaf(sh_misc[ci + 2], sh_sw[(ci + 2) * COUT + co], a2);
            a3 = fmaf(sh_misc[ci + 3], sh_sw[(ci + 3) * COUT + co], a3);
        }
        const float pooled = ((a0 + a1) + (a2 + a3)) * INV_OHW + bias;

        // block reduction over the 4 active warps (t<128)
        float m = warp_max(pooled);
        if (lane == 0) red[wid] = m;
        __syncthreads();
        const float m0 = fmaxf(fmaxf(red[0], red[1]), fmaxf(red[2], red[3]));

        float e = warp_sum(__expf(pooled - m0));
        if (lane == 0) red2[wid] = e;
        __syncthreads();
        if (t == 0) {
            float tot = (red2[0] + red2[1]) + (red2[2] + red2[3]);
            out[n] = 10.0f * (m0 + logf(tot));
        }
    } else {
        __syncthreads();   // match the two __syncthreads in the t<128 path
        __syncthreads();
    }

    // Last finalize block to complete resets the counters for graph replay.
    __syncthreads();
    if (t == 0) {
        unsigned k = atomicAdd(&g_done, 1u);
        if (k == NB - 1) {
            atomicExch(&g_count, 0u);
            atomicExch(&g_done, 0u);
        }
    }
}

extern "C" void kernel_launch(void* const* d_in, const int* in_sizes, int n_in,
                              void* d_out, int out_size) {
    const float* x  = (const float*)d_in[0];   // (32,64,64,64)
    const float* w  = (const float*)d_in[1];   // (64,128,4,4)
    const float* cb = (const float*)d_in[2];   // (128,)
    const float* eb = (const float*)d_in[3];   // (128,)
    float* out = (float*)d_out;                // (32,1)

    fused_kernel<<<GRID, 256>>>(x, w, cb, eb, out);
}

// round 6
// speedup vs baseline: 1.9624x; 1.9624x over previous
#include <cuda_runtime.h>
#include <math_constants.h>

#define NB   32
#define CIN  64
#define COUT 128
#define HW   4096               // 64*64 spatial per (n,ci)
#define INV_OHW (1.0f/4489.0f)  // 1/(67*67)
#define NXB  (NB * CIN)         // 2048 x-reduce blocks
#define GRID (NB + NXB + CIN)   // 32 finalize + 2048 x + 64 w = 2144

__device__ float g_Sx[NB * CIN];
__device__ float g_Sw[CIN * COUT];
__device__ unsigned g_cnt[NB * 32];   // one counter per batch row, 128B apart
__device__ unsigned g_wcnt = 0;
__device__ unsigned g_done = 0;

__device__ __forceinline__ void atom_inc_release(unsigned* p) {
    unsigned old;
    asm volatile("atom.add.release.gpu.u32 %0, [%1], 1;"
                 : "=r"(old) : "l"(p) : "memory");
}
__device__ __forceinline__ unsigned ld_acquire(const unsigned* p) {
    unsigned v;
    asm volatile("ld.acquire.gpu.u32 %0, [%1];" : "=r"(v) : "l"(p) : "memory");
    return v;
}

__device__ __forceinline__ float warp_sum(float v) {
    v += __shfl_xor_sync(0xffffffffu, v, 16);
    v += __shfl_xor_sync(0xffffffffu, v, 8);
    v += __shfl_xor_sync(0xffffffffu, v, 4);
    v += __shfl_xor_sync(0xffffffffu, v, 2);
    v += __shfl_xor_sync(0xffffffffu, v, 1);
    return v;
}
__device__ __forceinline__ float warp_max(float v) {
    v = fmaxf(v, __shfl_xor_sync(0xffffffffu, v, 16));
    v = fmaxf(v, __shfl_xor_sync(0xffffffffu, v, 8));
    v = fmaxf(v, __shfl_xor_sync(0xffffffffu, v, 4));
    v = fmaxf(v, __shfl_xor_sync(0xffffffffu, v, 2));
    v = fmaxf(v, __shfl_xor_sync(0xffffffffu, v, 1));
    return v;
}

__global__ void __launch_bounds__(256) fused_kernel(
    const float* __restrict__ x,
    const float* __restrict__ w,
    const float* __restrict__ cb,
    const float* __restrict__ eb,
    float* __restrict__ out)
{
    __shared__ float sh[CIN];      // x: cross-warp scratch(8) / fin: sx row(64)
    __shared__ float red[8], red2[8];

    const int bid  = blockIdx.x;
    const int t    = threadIdx.x;
    const int lane = t & 31;
    const int wid  = t >> 5;

    if (bid >= NB + NXB) {
        // ---------------- w-block: one per ci ----------------
        const int ci = bid - (NB + NXB);
        if (t < COUT) {
            const float4* p = reinterpret_cast<const float4*>(w)
                            + ((size_t)ci * COUT + t) * 4;
            float4 a0 = p[0], a1 = p[1], a2 = p[2], a3 = p[3];
            g_Sw[ci * COUT + t] =
                ((a0.x + a0.y) + (a0.z + a0.w)) +
                ((a1.x + a1.y) + (a1.z + a1.w)) +
                ((a2.x + a2.y) + (a2.z + a2.w)) +
                ((a3.x + a3.y) + (a3.z + a3.w));
        }
        __syncthreads();                       // all stores done block-wide
        if (t == 0) atom_inc_release(&g_wcnt); // transitively orders them
        return;
    }

    if (bid >= NB) {
        // ---------------- x-block: one per (n,ci) ----------------
        const int b = bid - NB;
        const float4* p = reinterpret_cast<const float4*>(x) + (size_t)b * (HW / 4);
        float s = 0.0f;
        #pragma unroll
        for (int i = 0; i < 4; i++) {
            float4 v = p[t + i * 256];
            s += (v.x + v.y) + (v.z + v.w);
        }
        s = warp_sum(s);
        if (lane == 0) sh[wid] = s;
        __syncthreads();
        if (t == 0) {
            float u = ((sh[0] + sh[1]) + (sh[2] + sh[3]))
                    + ((sh[4] + sh[5]) + (sh[6] + sh[7]));
            g_Sx[b] = u;
            atom_inc_release(&g_cnt[(b >> 6) * 32]);  // row counter (padded)
        }
        return;
    }

    // ---------------- finalize block: n = bid ----------------
    const int n  = bid;
    const int co = t;

    // Prefetch biases (cold DRAM) while everything else runs.
    const float bias = (co < COUT) ? (cb[co] + eb[co]) : 0.0f;

    // Wait for this row's 64 x-blocks and the 64 w-blocks.
    if (t == 0) {
        while (ld_acquire(&g_cnt[n * 32]) < CIN) __nanosleep(128);
        while (ld_acquire(&g_wcnt) < CIN)       __nanosleep(64);
    }
    __syncthreads();   // acquire by t0 happens-before everyone's reads

    if (t < CIN) sh[t] = g_Sx[n * CIN + t];
    __syncthreads();

    float pooled = -CUDART_INF_F;
    if (co < COUT) {
        float a0 = 0.f, a1 = 0.f, a2 = 0.f, a3 = 0.f;
        #pragma unroll
        for (int ci = 0; ci < CIN; ci += 4) {
            a0 = fmaf(sh[ci + 0], g_Sw[(ci + 0) * COUT + co], a0);
            a1 = fmaf(sh[ci + 1], g_Sw[(ci + 1) * COUT + co], a1);
            a2 = fmaf(sh[ci + 2], g_Sw[(ci + 2) * COUT + co], a2);
            a3 = fmaf(sh[ci + 3], g_Sw[(ci + 3) * COUT + co], a3);
        }
        pooled = ((a0 + a1) + (a2 + a3)) * INV_OHW + bias;
    }

    // LSE over all 8 warps (idle warps contribute neutral elements).
    float m = warp_max(pooled);
    if (lane == 0) red[wid] = m;
    __syncthreads();
    float m0 = red[0];
    #pragma unroll
    for (int i = 1; i < 8; i++) m0 = fmaxf(m0, red[i]);

    float e = warp_sum((co < COUT) ? __expf(pooled - m0) : 0.0f);
    if (lane == 0) red2[wid] = e;
    __syncthreads();

    if (t == 0) {
        float tot = ((red2[0] + red2[1]) + (red2[2] + red2[3]))
                  + ((red2[4] + red2[5]) + (red2[6] + red2[7]));
        out[n] = 10.0f * (m0 + logf(tot));

        // Reset for next graph replay.
        atomicExch(&g_cnt[n * 32], 0u);
        unsigned k = atomicAdd(&g_done, 1u);
        if (k == NB - 1) {
            atomicExch(&g_wcnt, 0u);
            atomicExch(&g_done, 0u);
        }
    }
}

extern "C" void kernel_launch(void* const* d_in, const int* in_sizes, int n_in,
                              void* d_out, int out_size) {
    const float* x  = (const float*)d_in[0];   // (32,64,64,64)
    const float* w  = (const float*)d_in[1];   // (64,128,4,4)
    const float* cb = (const float*)d_in[2];   // (128,)
    const float* eb = (const float*)d_in[3];   // (128,)
    float* out = (float*)d_out;                // (32,1)

    fused_kernel<<<GRID, 256>>>(x, w, cb, eb, out);
}

// round 7
// speedup vs baseline: 2.3373x; 1.1910x over previous
#include <cuda_runtime.h>

#define NB   32
#define CIN  64
#define COUT 128
#define HW   4096               // 64*64 spatial floats per (n,ci)
#define INV_OHW (1.0f/4489.0f)  // 1/(67*67)

#define ROWS_PER_BLK 2
#define NXB  (NB * CIN / ROWS_PER_BLK)   // 1024 x-blocks
#define NWB  CIN                          // 64 w-blocks
#define GRID (NXB + NWB)                  // 1088: single wave on 148 SMs

__device__ float g_Sx[NB * CIN];
__device__ float g_Sw[CIN * COUT];

__device__ __forceinline__ float warp_sum(float v) {
    v += __shfl_xor_sync(0xffffffffu, v, 16);
    v += __shfl_xor_sync(0xffffffffu, v, 8);
    v += __shfl_xor_sync(0xffffffffu, v, 4);
    v += __shfl_xor_sync(0xffffffffu, v, 2);
    v += __shfl_xor_sync(0xffffffffu, v, 1);
    return v;
}
__device__ __forceinline__ float warp_max(float v) {
    v = fmaxf(v, __shfl_xor_sync(0xffffffffu, v, 16));
    v = fmaxf(v, __shfl_xor_sync(0xffffffffu, v, 8));
    v = fmaxf(v, __shfl_xor_sync(0xffffffffu, v, 4));
    v = fmaxf(v, __shfl_xor_sync(0xffffffffu, v, 2));
    v = fmaxf(v, __shfl_xor_sync(0xffffffffu, v, 1));
    return v;
}

// Kernel 1: bandwidth-shaped reduction.
// x-block: 2 rows (32KB), 256 threads, 8 independent LDG.128 per thread.
__global__ void __launch_bounds__(256) reduce_kernel(
    const float* __restrict__ x,
    const float* __restrict__ w)
{
    const int b = blockIdx.x;
    const int t = threadIdx.x;
    const int lane = t & 31;
    const int wid  = t >> 5;

    if (b < NXB) {
        // rows r0 = 2b, r0+1; 2048 float4 per block
        const float4* p = reinterpret_cast<const float4*>(x)
                        + (size_t)b * (ROWS_PER_BLK * HW / 4);
        // Front-batch all 8 loads (independent -> MLP 8)
        float4 v0 = p[t];
        float4 v1 = p[t + 256];
        float4 v2 = p[t + 512];
        float4 v3 = p[t + 768];
        float4 v4 = p[t + 1024];
        float4 v5 = p[t + 1280];
        float4 v6 = p[t + 1536];
        float4 v7 = p[t + 1792];

        float s0 = ((v0.x + v0.y) + (v0.z + v0.w))
                 + ((v1.x + v1.y) + (v1.z + v1.w))
                 + ((v2.x + v2.y) + (v2.z + v2.w))
                 + ((v3.x + v3.y) + (v3.z + v3.w));
        float s1 = ((v4.x + v4.y) + (v4.z + v4.w))
                 + ((v5.x + v5.y) + (v5.z + v5.w))
                 + ((v6.x + v6.y) + (v6.z + v6.w))
                 + ((v7.x + v7.y) + (v7.z + v7.w));

        s0 = warp_sum(s0);
        s1 = warp_sum(s1);

        __shared__ float sh0[8], sh1[8];
        if (lane == 0) { sh0[wid] = s0; sh1[wid] = s1; }
        __syncthreads();
        if (t == 0) {
            float u0 = ((sh0[0] + sh0[1]) + (sh0[2] + sh0[3]))
                     + ((sh0[4] + sh0[5]) + (sh0[6] + sh0[7]));
            float u1 = ((sh1[0] + sh1[1]) + (sh1[2] + sh1[3]))
                     + ((sh1[4] + sh1[5]) + (sh1[6] + sh1[7]));
            g_Sx[b * 2]     = u0;
            g_Sx[b * 2 + 1] = u1;
        }
    } else {
        // w-block: one per ci, thread co sums its 16 contiguous taps
        const int ci = b - NXB;
        if (t < COUT) {
            const float4* p = reinterpret_cast<const float4*>(w)
                            + ((size_t)ci * COUT + t) * 4;
            float4 a0 = p[0], a1 = p[1], a2 = p[2], a3 = p[3];
            g_Sw[ci * COUT + t] =
                ((a0.x + a0.y) + (a0.z + a0.w)) +
                ((a1.x + a1.y) + (a1.z + a1.w)) +
                ((a2.x + a2.y) + (a2.z + a2.w)) +
                ((a3.x + a3.y) + (a3.z + a3.w));
        }
    }
}

// Kernel 2: one block per n, 128 threads (one per co). ~1us hot.
__global__ void __launch_bounds__(COUT) finalize_kernel(
    const float* __restrict__ cb,
    const float* __restrict__ eb,
    float* __restrict__ out)
{
    const int n  = blockIdx.x;
    const int co = threadIdx.x;
    const int lane = co & 31;
    const int wid  = co >> 5;

    __shared__ float sx[CIN];
    if (co < CIN) sx[co] = g_Sx[n * CIN + co];
    __syncthreads();

    float a0 = 0.f, a1 = 0.f, a2 = 0.f, a3 = 0.f;
    #pragma unroll
    for (int ci = 0; ci < CIN; ci += 4) {
        a0 = fmaf(sx[ci + 0], g_Sw[(ci + 0) * COUT + co], a0);
        a1 = fmaf(sx[ci + 1], g_Sw[(ci + 1) * COUT + co], a1);
        a2 = fmaf(sx[ci + 2], g_Sw[(ci + 2) * COUT + co], a2);
        a3 = fmaf(sx[ci + 3], g_Sw[(ci + 3) * COUT + co], a3);
    }
    const float pooled = ((a0 + a1) + (a2 + a3)) * INV_OHW + cb[co] + eb[co];

    __shared__ float red[4], red2[4];
    float m = warp_max(pooled);
    if (lane == 0) red[wid] = m;
    __syncthreads();
    const float m0 = fmaxf(fmaxf(red[0], red[1]), fmaxf(red[2], red[3]));

    float e = warp_sum(__expf(pooled - m0));
    if (lane == 0) red2[wid] = e;
    __syncthreads();
    if (co == 0) {
        float tot = (red2[0] + red2[1]) + (red2[2] + red2[3]);
        out[n] = 10.0f * (m0 + logf(tot));
    }
}

extern "C" void kernel_launch(void* const* d_in, const int* in_sizes, int n_in,
                              void* d_out, int out_size) {
    const float* x  = (const float*)d_in[0];   // (32,64,64,64)
    const float* w  = (const float*)d_in[1];   // (64,128,4,4)
    const float* cb = (const float*)d_in[2];   // (128,)
    const float* eb = (const float*)d_in[3];   // (128,)
    float* out = (float*)d_out;                // (32,1)

    reduce_kernel<<<GRID, 256>>>(x, w);
    finalize_kernel<<<NB, COUT>>>(cb, eb, out);
}